// round 15
// baseline (speedup 1.0000x reference)
#include <cuda_runtime.h>
#include <cuda_fp16.h>
#include <math.h>
#include <stdint.h>

#define BB 2
#define TT 2048
#define DD 2048
#define HH 16
#define HKK 4
#define HDD 128
#define REP 4
#define ROWS (BB*TT)   // 4096

// ---------------- scratch (no cudaMalloc allowed) ----------------
__device__ __align__(256) __half g_xh  [(size_t)ROWS*DD];      // 16MB
__device__ __align__(256) __half g_qh  [(size_t)ROWS*HH*HDD];  // 16MB
__device__ __align__(256) __half g_kvh [(size_t)ROWS*1024];    // 8MB  (k 0-511 | v 512-1023)
__device__ __align__(256) __half g_atth[(size_t)ROWS*HH*HDD];  // 16MB
__device__ __align__(256) __half g_wqT [(size_t)DD*DD];        // 8MB  [N][K]
__device__ __align__(256) __half g_wkvT[(size_t)1024*DD];      // 4MB
__device__ __align__(256) __half g_woT [(size_t)DD*DD];        // 8MB

// Side stream + events (static-init; host-side only).
struct ForkResources {
    cudaStream_t s1 = nullptr;
    cudaEvent_t  e_fork = nullptr, e_join = nullptr;
    bool ok = false;
    ForkResources() {
        ok = (cudaStreamCreateWithFlags(&s1, cudaStreamNonBlocking) == cudaSuccess) &&
             (cudaEventCreateWithFlags(&e_fork, cudaEventDisableTiming) == cudaSuccess) &&
             (cudaEventCreateWithFlags(&e_join, cudaEventDisableTiming) == cudaSuccess);
    }
};
static ForkResources g_fork;

// ---------------- primitives ----------------
__device__ __forceinline__ void mma_f16(float* d, const uint32_t* a, const uint32_t* b) {
    asm volatile(
        "mma.sync.aligned.m16n8k16.row.col.f32.f16.f16.f32 "
        "{%0,%1,%2,%3}, {%4,%5,%6,%7}, {%8,%9}, {%0,%1,%2,%3};\n"
        : "+f"(d[0]), "+f"(d[1]), "+f"(d[2]), "+f"(d[3])
        : "r"(a[0]), "r"(a[1]), "r"(a[2]), "r"(a[3]), "r"(b[0]), "r"(b[1]));
}
__device__ __forceinline__ void ldmatrix_x4(uint32_t* r, uint32_t saddr) {
    asm volatile(
        "ldmatrix.sync.aligned.m8n8.x4.shared.b16 {%0,%1,%2,%3}, [%4];"
        : "=r"(r[0]), "=r"(r[1]), "=r"(r[2]), "=r"(r[3]) : "r"(saddr));
}
__device__ __forceinline__ void ldmatrix_x4_trans(uint32_t* r, uint32_t saddr) {
    asm volatile(
        "ldmatrix.sync.aligned.m8n8.x4.trans.shared.b16 {%0,%1,%2,%3}, [%4];"
        : "=r"(r[0]), "=r"(r[1]), "=r"(r[2]), "=r"(r[3]) : "r"(saddr));
}
__device__ __forceinline__ void cp16(uint32_t saddr, const void* g) {
    asm volatile("cp.async.cg.shared.global [%0], [%1], 16;\n" :: "r"(saddr), "l"(g));
}
__device__ __forceinline__ uint32_t packh2(float a, float b) {
    __half2 h = __floats2half2_rn(a, b);
    return *reinterpret_cast<uint32_t*>(&h);
}

// ---------------------------------------------------------------------------
// Fused prepass (unchanged R13): z<4 -> weight transposes, z>=4 -> x f32->f16.
// ---------------------------------------------------------------------------
__global__ void prepass_all(const float* __restrict__ x, __half* __restrict__ xh,
                            const float* __restrict__ wq, const float* __restrict__ wk,
                            const float* __restrict__ wv, const float* __restrict__ wo,
                            __half* __restrict__ wqT, __half* __restrict__ wkvT,
                            __half* __restrict__ woT)
{
    const int z = blockIdx.z;
    if (z >= 4) {
        int i = ((z - 4) * 4096 + blockIdx.y * 64 + blockIdx.x) * 256 + threadIdx.y * 32 + threadIdx.x;
        const int n4 = ROWS * DD / 4;
        if (i >= n4) return;
        float4 v = reinterpret_cast<const float4*>(x)[i];
        uint2 o;
        o.x = packh2(v.x, v.y);
        o.y = packh2(v.z, v.w);
        reinterpret_cast<uint2*>(xh)[i] = o;
        return;
    }
    __shared__ float t[32][33];
    const float* in;
    __half* out;
    int C;
    if (z == 0)      { in = wq; out = wqT;  C = 2048; }
    else if (z == 1) { in = wk; out = wkvT; C = 512;  }
    else if (z == 2) { in = wv; out = wkvT + (size_t)512 * DD; C = 512; }
    else             { in = wo; out = woT;  C = 2048; }
    int c0 = blockIdx.x * 32, r0 = blockIdx.y * 32;
    if (c0 >= C) return;
    #pragma unroll
    for (int i = 0; i < 32; i += 8)
        t[threadIdx.y + i][threadIdx.x] =
            in[(size_t)(r0 + threadIdx.y + i) * C + c0 + threadIdx.x];
    __syncthreads();
    #pragma unroll
    for (int i = 0; i < 32; i += 8)
        out[(size_t)(c0 + threadIdx.y + i) * 2048 + r0 + threadIdx.x] =
            __float2half_rn(t[threadIdx.x][threadIdx.y + i]);
}

// ---------------- RoPE (interleaved pairs) on half ----------------
__global__ void rope_h(__half* __restrict__ x,
                       const float* __restrict__ cs, const float* __restrict__ sn,
                       int nh, int row_stride, int total, float scale)
{
    int idx = blockIdx.x * blockDim.x + threadIdx.x;
    if (idx >= total) return;
    int i    = idx % (HDD / 2);
    int rest = idx / (HDD / 2);
    int h    = rest % nh;
    int row  = rest / nh;
    int t    = row % TT;
    float c = cs[t * (HDD / 2) + i];
    float s = sn[t * (HDD / 2) + i];
    __half2* p = reinterpret_cast<__half2*>(x + (size_t)row * row_stride + h * HDD) + i;
    float2 v = __half22float2(*p);
    *p = __floats2half2_rn((v.x * c - v.y * s) * scale, (v.x * s + v.y * c) * scale);
}

// ---------------------------------------------------------------------------
// fp16 GEMM: CTA tile 128x128, 256 threads (8 warps, 2x4, warp tile 64x32),
// BK=64, 3-stage cp.async, 2 CTAs/SM (smem 110592/CTA, regs forced <=128).
// Per-output K-summation order identical to the 128x256 version.
// ---------------------------------------------------------------------------
#define GBM 128
#define GBN 128
#define GKC 64
#define HSTR 72
#define A_H (GBM*HSTR)
#define B_H (GBN*HSTR)
#define STG_B ((A_H + B_H) * 2)        // 36864 B/stage
#define GEMM_SMEM (3 * STG_B)          // 110592

__global__ void __launch_bounds__(256, 2) gemm_h(
    int M, int N, int K,
    const __half* __restrict__ A, const __half* __restrict__ Bt,
    void* __restrict__ Cv, int half_out)
{
    extern __shared__ __half sh[];
    const uint32_t smem_base = (uint32_t)__cvta_generic_to_shared(sh);
    const uint32_t* shw = reinterpret_cast<const uint32_t*>(sh);

    const int tid  = threadIdx.x;
    const int lane = tid & 31;
    const int wid  = tid >> 5;          // 0..7
    const int wm   = wid >> 2;          // 0..1
    const int wn   = wid & 3;           // 0..3
    const int rowBase = blockIdx.y * GBM;
    const int colBase = blockIdx.x * GBN;
    const int nk = K / GKC;

    float acc[4][4][4];                 // 4 m-tiles x 4 n-tiles x 4
    #pragma unroll
    for (int mt = 0; mt < 4; mt++)
        #pragma unroll
        for (int nt = 0; nt < 4; nt++)
            #pragma unroll
            for (int j = 0; j < 4; j++) acc[mt][nt][j] = 0.0f;

    auto issue = [&](int s) {
        int k0 = s * GKC;
        uint32_t sA = smem_base + (uint32_t)((s % 3) * STG_B);
        uint32_t sB = sA + (uint32_t)(A_H * 2);
        #pragma unroll
        for (int i = 0; i < 4; i++) {          // A: 128x64 = 1024 chunks
            int idx = tid + i * 256;
            int r = idx >> 3, c = idx & 7;
            cp16(sA + (uint32_t)(r * HSTR + c * 8) * 2u,
                 A + (size_t)(rowBase + r) * K + k0 + c * 8);
        }
        #pragma unroll
        for (int i = 0; i < 4; i++) {          // B: 128x64 = 1024 chunks
            int idx = tid + i * 256;
            int r = idx >> 3, c = idx & 7;
            cp16(sB + (uint32_t)(r * HSTR + c * 8) * 2u,
                 Bt + (size_t)(colBase + r) * K + k0 + c * 8);
        }
        asm volatile("cp.async.commit_group;\n" ::: "memory");
    };

    issue(0);
    issue(1);

    const int c4 = lane & 3;
    const int g4 = lane >> 2;

    for (int s = 0; s < nk; s++) {
        asm volatile("cp.async.wait_group 1;\n" ::: "memory");
        __syncthreads();
        if (s + 2 < nk) issue(s + 2);

        const uint32_t* Aw = shw + (s % 3) * (STG_B / 4);
        const uint32_t* Bw = Aw + A_H / 2;
        const int WSTR = HSTR / 2;

        #pragma unroll
        for (int k16 = 0; k16 < 4; k16++) {
            const int kw = k16 * 8;
            uint32_t a[4][4], b[4][2];
            #pragma unroll
            for (int mt = 0; mt < 4; mt++) {
                int r = wm * 64 + mt * 16 + g4;
                a[mt][0] = Aw[r * WSTR + kw + c4];
                a[mt][1] = Aw[(r + 8) * WSTR + kw + c4];
                a[mt][2] = Aw[r * WSTR + kw + 4 + c4];
                a[mt][3] = Aw[(r + 8) * WSTR + kw + 4 + c4];
            }
            #pragma unroll
            for (int nt = 0; nt < 4; nt++) {
                int n = wn * 32 + nt * 8 + g4;
                b[nt][0] = Bw[n * WSTR + kw + c4];
                b[nt][1] = Bw[n * WSTR + kw + 4 + c4];
            }
            #pragma unroll
            for (int mt = 0; mt < 4; mt++)
                #pragma unroll
                for (int nt = 0; nt < 4; nt++)
                    mma_f16(acc[mt][nt], a[mt], b[nt]);
        }
        __syncthreads();
    }

    if (half_out) {
        __half* C = (__half*)Cv;
        #pragma unroll
        for (int mt = 0; mt < 4; mt++) {
            int r0 = rowBase + wm * 64 + mt * 16 + g4;
            #pragma unroll
            for (int nt = 0; nt < 4; nt++) {
                int c0 = colBase + wn * 32 + nt * 8 + 2 * c4;
                *reinterpret_cast<__half2*>(C + (size_t)r0 * N + c0) =
                    __floats2half2_rn(acc[mt][nt][0], acc[mt][nt][1]);
                *reinterpret_cast<__half2*>(C + (size_t)(r0 + 8) * N + c0) =
                    __floats2half2_rn(acc[mt][nt][2], acc[mt][nt][3]);
            }
        }
    } else {
        float* C = (float*)Cv;
        #pragma unroll
        for (int mt = 0; mt < 4; mt++) {
            int r0 = rowBase + wm * 64 + mt * 16 + g4;
            #pragma unroll
            for (int nt = 0; nt < 4; nt++) {
                int c0 = colBase + wn * 32 + nt * 8 + 2 * c4;
                *reinterpret_cast<float2*>(C + (size_t)r0 * N + c0) =
                    make_float2(acc[mt][nt][0], acc[mt][nt][1]);
                *reinterpret_cast<float2*>(C + (size_t)(r0 + 8) * N + c0) =
                    make_float2(acc[mt][nt][2], acc[mt][nt][3]);
            }
        }
    }
}

// ---------------------------------------------------------------------------
// fp16 flash attention — unchanged R11 (BR=64, 128 threads, 2 CTAs/SM).
// ---------------------------------------------------------------------------
#define FBR 64
#define FSTR 136
#define FWSTR 68
#define KVH (64*FSTR)
#define FLASH_SMEM (4*KVH*2)             // 69632

__global__ void __launch_bounds__(128, 2) flash_h(
    const __half* __restrict__ q, const __half* __restrict__ kv,
    __half* __restrict__ att)
{
    extern __shared__ __half sh[];
    const uint32_t smem_base = (uint32_t)__cvta_generic_to_shared(sh);

    const int tid  = threadIdx.x;
    const int lane = tid & 31;
    const int wid  = tid >> 5;
    const int bx = gridDim.x - 1 - blockIdx.x;
    const int h = blockIdx.y, b = blockIdx.z;
    const int hk = h / REP;
    const int qrow0 = bx * FBR;
    const int c4 = lane & 3;
    const int g4 = lane >> 2;

    {
        const __half* qg = q + ((size_t)(b * TT + qrow0) * HH + h) * HDD;
        #pragma unroll
        for (int i = 0; i < 8; i++) {
            int idx = tid + i * 128;
            int r = idx >> 4, c = idx & 15;
            *reinterpret_cast<uint4*>(sh + r * FSTR + c * 8) =
                *reinterpret_cast<const uint4*>(qg + (size_t)r * HH * HDD + c * 8);
        }
    }
    __syncthreads();

    uint32_t qa[8][4];
    {
        const uint32_t* Qw = reinterpret_cast<const uint32_t*>(sh);
        const int r = wid * 16 + g4;
        #pragma unroll
        for (int ks = 0; ks < 8; ks++) {
            int w = ks * 8 + c4;
            qa[ks][0] = Qw[r * FWSTR + w];
            qa[ks][1] = Qw[(r + 8) * FWSTR + w];
            qa[ks][2] = Qw[r * FWSTR + w + 4];
            qa[ks][3] = Qw[(r + 8) * FWSTR + w + 4];
        }
    }
    __syncthreads();

    auto issue_kv = [&](int kt, int stg) {
        const __half* kg = kv + (size_t)(b * TT + kt * 64) * 1024 + hk * HDD;
        uint32_t ks_u = smem_base + (uint32_t)(stg * 2 * KVH) * 2u;
        uint32_t vs_u = ks_u + (uint32_t)KVH * 2u;
        #pragma unroll
        for (int i = 0; i < 16; i++) {
            int idx = tid + i * 128;
            int r = (idx >> 4) & 63, c = idx & 15;
            if (idx < 1024)
                cp16(ks_u + (uint32_t)(r * FSTR + c * 8) * 2u,
                     kg + (size_t)r * 1024 + c * 8);
            else
                cp16(vs_u + (uint32_t)(r * FSTR + c * 8) * 2u,
                     kg + 512 + (size_t)r * 1024 + c * 8);
        }
        asm volatile("cp.async.commit_group;\n" ::: "memory");
    };

    float o[16][4];
    #pragma unroll
    for (int nt = 0; nt < 16; nt++)
        #pragma unroll
        for (int j = 0; j < 4; j++) o[nt][j] = 0.0f;

    float m0 = -INFINITY, m1 = -INFINITY, l0 = 0.0f, l1 = 0.0f;
    const int r0g = qrow0 + wid * 16 + g4;
    const int r1g = r0g + 8;

    const uint32_t k_lane_off =
        (uint32_t)(((lane & 7) + ((lane >> 4) << 3)) * FSTR + ((lane >> 3) & 1) * 8);

    const int ntile = bx + 1;
    issue_kv(0, 0);

    for (int kt = 0; kt < ntile; kt++) {
        __syncthreads();
        if (kt + 1 < ntile) {
            issue_kv(kt + 1, (kt + 1) & 1);
            asm volatile("cp.async.wait_group 1;\n" ::: "memory");
        } else {
            asm volatile("cp.async.wait_group 0;\n" ::: "memory");
        }
        __syncthreads();

        const uint32_t ks_base = smem_base + (uint32_t)((kt & 1) * 2 * KVH) * 2u;
        const uint32_t vs_base = ks_base + (uint32_t)KVH * 2u;

        float s[8][4];
        #pragma unroll
        for (int nt = 0; nt < 8; nt++)
            #pragma unroll
            for (int j = 0; j < 4; j++) s[nt][j] = 0.0f;

        #pragma unroll
        for (int ks = 0; ks < 8; ks++) {
            #pragma unroll
            for (int np = 0; np < 4; np++) {
                uint32_t bb[4];
                ldmatrix_x4(bb, ks_base +
                    (uint32_t)(np * 16 * FSTR + ks * 16 + k_lane_off) * 2u);
                mma_f16(s[2*np],     qa[ks], bb);
                mma_f16(s[2*np + 1], qa[ks], bb + 2);
            }
        }

        if (kt >= bx) {
            #pragma unroll
            for (int nt = 0; nt < 8; nt++) {
                int c0 = kt * 64 + nt * 8 + 2 * c4;
                if (c0     > r0g) s[nt][0] = -INFINITY;
                if (c0 + 1 > r0g) s[nt][1] = -INFINITY;
                if (c0     > r1g) s[nt][2] = -INFINITY;
                if (c0 + 1 > r1g) s[nt][3] = -INFINITY;
            }
        }

        float mx0 = -INFINITY, mx1 = -INFINITY;
        #pragma unroll
        for (int nt = 0; nt < 8; nt++) {
            mx0 = fmaxf(mx0, fmaxf(s[nt][0], s[nt][1]));
            mx1 = fmaxf(mx1, fmaxf(s[nt][2], s[nt][3]));
        }
        mx0 = fmaxf(mx0, __shfl_xor_sync(0xffffffffu, mx0, 1));
        mx0 = fmaxf(mx0, __shfl_xor_sync(0xffffffffu, mx0, 2));
        mx1 = fmaxf(mx1, __shfl_xor_sync(0xffffffffu, mx1, 1));
        mx1 = fmaxf(mx1, __shfl_xor_sync(0xffffffffu, mx1, 2));

        float nm0 = fmaxf(m0, mx0), nm1 = fmaxf(m1, mx1);
        float al0 = __expf(m0 - nm0), al1 = __expf(m1 - nm1);
        m0 = nm0; m1 = nm1;

        uint32_t ph0[8], ph1[8];
        float ps0 = 0.0f, ps1 = 0.0f;
        #pragma unroll
        for (int nt = 0; nt < 8; nt++) {
            ph0[nt] = packh2(__expf(s[nt][0] - nm0), __expf(s[nt][1] - nm0));
            ph1[nt] = packh2(__expf(s[nt][2] - nm1), __expf(s[nt][3] - nm1));
            float2 f0 = __half22float2(*reinterpret_cast<__half2*>(&ph0[nt]));
            float2 f1 = __half22float2(*reinterpret_cast<__half2*>(&ph1[nt]));
            ps0 += f0.x + f0.y;
            ps1 += f1.x + f1.y;
        }
        ps0 += __shfl_xor_sync(0xffffffffu, ps0, 1);
        ps0 += __shfl_xor_sync(0xffffffffu, ps0, 2);
        ps1 += __shfl_xor_sync(0xffffffffu, ps1, 1);
        ps1 += __shfl_xor_sync(0xffffffffu, ps1, 2);
        l0 = l0 * al0 + ps0;
        l1 = l1 * al1 + ps1;

        #pragma unroll
        for (int nt = 0; nt < 16; nt++) {
            o[nt][0] *= al0; o[nt][1] *= al0;
            o[nt][2] *= al1; o[nt][3] *= al1;
        }

        const int lm = lane >> 3;
        const int lr = lane & 7;
        #pragma unroll
        for (int ks2 = 0; ks2 < 4; ks2++) {
            uint32_t pa[4] = { ph0[2*ks2], ph1[2*ks2], ph0[2*ks2+1], ph1[2*ks2+1] };
            #pragma unroll
            for (int nb = 0; nb < 8; nb++) {
                uint32_t vb[4];
                int srow = ks2 * 16 + (lm & 1) * 8 + lr;
                int dcol = nb * 16 + (lm >> 1) * 8;
                ldmatrix_x4_trans(vb, vs_base + (uint32_t)(srow * FSTR + dcol) * 2u);
                mma_f16(o[2*nb],     pa, vb);
                mma_f16(o[2*nb + 1], pa, vb + 2);
            }
        }
    }

    const float inv0 = 1.0f / l0, inv1 = 1.0f / l1;
    #pragma unroll
    for (int nt2 = 0; nt2 < 16; nt2++) {
        int c = h * HDD + nt2 * 8 + 2 * c4;
        size_t base0 = (size_t)(b * TT + r0g) * (HH * HDD) + c;
        size_t base1 = (size_t)(b * TT + r1g) * (HH * HDD) + c;
        *reinterpret_cast<__half2*>(att + base0) =
            __floats2half2_rn(o[nt2][0] * inv0, o[nt2][1] * inv0);
        *reinterpret_cast<__half2*>(att + base1) =
            __floats2half2_rn(o[nt2][2] * inv1, o[nt2][3] * inv1);
    }
}

// ---------------------------------------------------------------------------
extern "C" void kernel_launch(void* const* d_in, const int* in_sizes, int n_in,
                              void* d_out, int out_size)
{
    const float* x  = (const float*)d_in[0];
    const float* fc = (const float*)d_in[1];
    const float* fs = (const float*)d_in[2];
    // d_in[3] = mask — enforced analytically
    const float* wq = (const float*)d_in[4];
    const float* wk = (const float*)d_in[5];
    const float* wv = (const float*)d_in[6];
    const float* wo = (const float*)d_in[7];
    float* out = (float*)d_out;

    __half *xh, *qh, *kvh, *atth, *wqT, *wkvT, *woT;
    cudaGetSymbolAddress((void**)&xh,   g_xh);
    cudaGetSymbolAddress((void**)&qh,   g_qh);
    cudaGetSymbolAddress((void**)&kvh,  g_kvh);
    cudaGetSymbolAddress((void**)&atth, g_atth);
    cudaGetSymbolAddress((void**)&wqT,  g_wqT);
    cudaGetSymbolAddress((void**)&wkvT, g_wkvT);
    cudaGetSymbolAddress((void**)&woT,  g_woT);

    cudaFuncSetAttribute(gemm_h,  cudaFuncAttributeMaxDynamicSharedMemorySize, GEMM_SMEM);
    cudaFuncSetAttribute(flash_h, cudaFuncAttributeMaxDynamicSharedMemorySize, (int)FLASH_SMEM);

    const int totq = ROWS * HH  * (HDD / 2);
    const int totk = ROWS * HKK * (HDD / 2);

    // 1) all prepasses in ONE launch
    prepass_all<<<dim3(64, 64, 6), dim3(32, 8)>>>(x, xh, wq, wk, wv, wo, wqT, wkvT, woT);

    if (g_fork.ok) {
        cudaEventRecord(g_fork.e_fork, 0);
        cudaStreamWaitEvent(g_fork.s1, g_fork.e_fork, 0);

        gemm_h<<<dim3(DD/GBN, ROWS/GBM), 256, GEMM_SMEM>>>(
            ROWS, DD, DD, xh, wqT, qh, 1);
        rope_h<<<(totq + 255)/256, 256>>>(qh, fc, fs, HH, HH*HDD, totq,
                                          0.08838834764831845f);

        gemm_h<<<dim3(1024/GBN, ROWS/GBM), 256, GEMM_SMEM, g_fork.s1>>>(
            ROWS, 1024, DD, xh, wkvT, kvh, 1);
        rope_h<<<(totk + 255)/256, 256, 0, g_fork.s1>>>(kvh, fc, fs, HKK, 1024, totk, 1.0f);

        cudaEventRecord(g_fork.e_join, g_fork.s1);
        cudaStreamWaitEvent(0, g_fork.e_join, 0);
    } else {
        gemm_h<<<dim3(DD/GBN, ROWS/GBM), 256, GEMM_SMEM>>>(ROWS, DD,   DD, xh, wqT,  qh,  1);
        gemm_h<<<dim3(1024/GBN, ROWS/GBM), 256, GEMM_SMEM>>>(ROWS, 1024, DD, xh, wkvT, kvh, 1);
        rope_h<<<(totq + 255)/256, 256>>>(qh,  fc, fs, HH,  HH*HDD, totq, 0.08838834764831845f);
        rope_h<<<(totk + 255)/256, 256>>>(kvh, fc, fs, HKK, 1024,   totk, 1.0f);
    }

    // flash attention (unchanged R11)
    flash_h<<<dim3(TT/FBR, HH, BB), 128, FLASH_SMEM>>>(qh, kvh, atth);

    // output projection (fp32 out)
    gemm_h<<<dim3(DD/GBN, ROWS/GBM), 256, GEMM_SMEM>>>(ROWS, DD, HH*HDD, atth, woT, out, 0);
}

// round 16
// speedup vs baseline: 1.0827x; 1.0827x over previous
#include <cuda_runtime.h>
#include <cuda_fp16.h>
#include <math.h>
#include <stdint.h>

#define BB 2
#define TT 2048
#define DD 2048
#define HH 16
#define HKK 4
#define HDD 128
#define REP 4
#define ROWS (BB*TT)   // 4096

// ---------------- scratch (no cudaMalloc allowed) ----------------
__device__ __align__(256) __half g_xh  [(size_t)ROWS*DD];      // 16MB
__device__ __align__(256) __half g_qh  [(size_t)ROWS*HH*HDD];  // 16MB
__device__ __align__(256) __half g_kvh [(size_t)ROWS*1024];    // 8MB  (k 0-511 | v 512-1023)
__device__ __align__(256) __half g_atth[(size_t)ROWS*HH*HDD];  // 16MB
__device__ __align__(256) __half g_wqT [(size_t)DD*DD];        // 8MB  [N][K]
__device__ __align__(256) __half g_wkvT[(size_t)1024*DD];      // 4MB
__device__ __align__(256) __half g_woT [(size_t)DD*DD];        // 8MB

// Side stream + events (static-init; host-side only).
struct ForkResources {
    cudaStream_t s1 = nullptr;
    cudaEvent_t  e_fork = nullptr, e_join = nullptr;
    bool ok = false;
    ForkResources() {
        ok = (cudaStreamCreateWithFlags(&s1, cudaStreamNonBlocking) == cudaSuccess) &&
             (cudaEventCreateWithFlags(&e_fork, cudaEventDisableTiming) == cudaSuccess) &&
             (cudaEventCreateWithFlags(&e_join, cudaEventDisableTiming) == cudaSuccess);
    }
};
static ForkResources g_fork;

// ---------------- primitives ----------------
__device__ __forceinline__ void mma_f16(float* d, const uint32_t* a, const uint32_t* b) {
    asm volatile(
        "mma.sync.aligned.m16n8k16.row.col.f32.f16.f16.f32 "
        "{%0,%1,%2,%3}, {%4,%5,%6,%7}, {%8,%9}, {%0,%1,%2,%3};\n"
        : "+f"(d[0]), "+f"(d[1]), "+f"(d[2]), "+f"(d[3])
        : "r"(a[0]), "r"(a[1]), "r"(a[2]), "r"(a[3]), "r"(b[0]), "r"(b[1]));
}
__device__ __forceinline__ void ldmatrix_x4(uint32_t* r, uint32_t saddr) {
    asm volatile(
        "ldmatrix.sync.aligned.m8n8.x4.shared.b16 {%0,%1,%2,%3}, [%4];"
        : "=r"(r[0]), "=r"(r[1]), "=r"(r[2]), "=r"(r[3]) : "r"(saddr));
}
__device__ __forceinline__ void ldmatrix_x4_trans(uint32_t* r, uint32_t saddr) {
    asm volatile(
        "ldmatrix.sync.aligned.m8n8.x4.trans.shared.b16 {%0,%1,%2,%3}, [%4];"
        : "=r"(r[0]), "=r"(r[1]), "=r"(r[2]), "=r"(r[3]) : "r"(saddr));
}
__device__ __forceinline__ void cp16(uint32_t saddr, const void* g) {
    asm volatile("cp.async.cg.shared.global [%0], [%1], 16;\n" :: "r"(saddr), "l"(g));
}
__device__ __forceinline__ uint32_t packh2(float a, float b) {
    __half2 h = __floats2half2_rn(a, b);
    return *reinterpret_cast<uint32_t*>(&h);
}

// ---------------------------------------------------------------------------
// Fused prepass (unchanged R13): z<4 -> weight transposes, z>=4 -> x f32->f16.
// ---------------------------------------------------------------------------
__global__ void prepass_all(const float* __restrict__ x, __half* __restrict__ xh,
                            const float* __restrict__ wq, const float* __restrict__ wk,
                            const float* __restrict__ wv, const float* __restrict__ wo,
                            __half* __restrict__ wqT, __half* __restrict__ wkvT,
                            __half* __restrict__ woT)
{
    const int z = blockIdx.z;
    if (z >= 4) {
        int i = ((z - 4) * 4096 + blockIdx.y * 64 + blockIdx.x) * 256 + threadIdx.y * 32 + threadIdx.x;
        const int n4 = ROWS * DD / 4;
        if (i >= n4) return;
        float4 v = reinterpret_cast<const float4*>(x)[i];
        uint2 o;
        o.x = packh2(v.x, v.y);
        o.y = packh2(v.z, v.w);
        reinterpret_cast<uint2*>(xh)[i] = o;
        return;
    }
    __shared__ float t[32][33];
    const float* in;
    __half* out;
    int C;
    if (z == 0)      { in = wq; out = wqT;  C = 2048; }
    else if (z == 1) { in = wk; out = wkvT; C = 512;  }
    else if (z == 2) { in = wv; out = wkvT + (size_t)512 * DD; C = 512; }
    else             { in = wo; out = woT;  C = 2048; }
    int c0 = blockIdx.x * 32, r0 = blockIdx.y * 32;
    if (c0 >= C) return;
    #pragma unroll
    for (int i = 0; i < 32; i += 8)
        t[threadIdx.y + i][threadIdx.x] =
            in[(size_t)(r0 + threadIdx.y + i) * C + c0 + threadIdx.x];
    __syncthreads();
    #pragma unroll
    for (int i = 0; i < 32; i += 8)
        out[(size_t)(c0 + threadIdx.y + i) * 2048 + r0 + threadIdx.x] =
            __float2half_rn(t[threadIdx.x][threadIdx.y + i]);
}

// ---------------- RoPE (interleaved pairs) on half ----------------
__global__ void rope_h(__half* __restrict__ x,
                       const float* __restrict__ cs, const float* __restrict__ sn,
                       int nh, int row_stride, int total, float scale)
{
    int idx = blockIdx.x * blockDim.x + threadIdx.x;
    if (idx >= total) return;
    int i    = idx % (HDD / 2);
    int rest = idx / (HDD / 2);
    int h    = rest % nh;
    int row  = rest / nh;
    int t    = row % TT;
    float c = cs[t * (HDD / 2) + i];
    float s = sn[t * (HDD / 2) + i];
    __half2* p = reinterpret_cast<__half2*>(x + (size_t)row * row_stride + h * HDD) + i;
    float2 v = __half22float2(*p);
    *p = __floats2half2_rn((v.x * c - v.y * s) * scale, (v.x * s + v.y * c) * scale);
}

// ---------------------------------------------------------------------------
// fp16 GEMM: CTA 128x256, BK=64, 3-stage cp.async, 512 threads (16 warps, 4x4),
// warp tile 32x64.  R16 change: fragments via ldmatrix.x4 (6 instrs/warp/k16
// instead of 24 scalar LDS) — identical fragments and accumulation order.
// ---------------------------------------------------------------------------
#define GBM 128
#define GBN 256
#define GKC 64
#define HSTR 72
#define A_H (GBM*HSTR)
#define B_H (GBN*HSTR)
#define STG_B ((A_H + B_H) * 2)
#define GEMM_SMEM (3 * STG_B)

__global__ void __launch_bounds__(512, 1) gemm_h(
    int M, int N, int K,
    const __half* __restrict__ A, const __half* __restrict__ Bt,
    void* __restrict__ Cv, int half_out)
{
    extern __shared__ __half sh[];
    const uint32_t smem_base = (uint32_t)__cvta_generic_to_shared(sh);

    const int tid  = threadIdx.x;
    const int lane = tid & 31;
    const int wid  = tid >> 5;
    const int wm   = wid >> 2;
    const int wn   = wid & 3;
    const int rowBase = blockIdx.y * GBM;
    const int colBase = blockIdx.x * GBN;
    const int nk = K / GKC;

    float acc[2][8][4];
    #pragma unroll
    for (int mt = 0; mt < 2; mt++)
        #pragma unroll
        for (int nt = 0; nt < 8; nt++)
            #pragma unroll
            for (int j = 0; j < 4; j++) acc[mt][nt][j] = 0.0f;

    auto issue = [&](int s) {
        int k0 = s * GKC;
        uint32_t sA = smem_base + (uint32_t)((s % 3) * STG_B);
        uint32_t sB = sA + (uint32_t)(A_H * 2);
        #pragma unroll
        for (int i = 0; i < 2; i++) {
            int idx = tid + i * 512;
            int r = idx >> 3, c = idx & 7;
            cp16(sA + (uint32_t)(r * HSTR + c * 8) * 2u,
                 A + (size_t)(rowBase + r) * K + k0 + c * 8);
        }
        #pragma unroll
        for (int i = 0; i < 4; i++) {
            int idx = tid + i * 512;
            int r = idx >> 3, c = idx & 7;
            cp16(sB + (uint32_t)(r * HSTR + c * 8) * 2u,
                 Bt + (size_t)(colBase + r) * K + k0 + c * 8);
        }
        asm volatile("cp.async.commit_group;\n" ::: "memory");
    };

    issue(0);
    issue(1);

    const int c4 = lane & 3;
    const int g4 = lane >> 2;

    // ldmatrix lane offsets (in halves):
    // A matrices: (m0-7,k0-7),(m8-15,k0-7),(m0-7,k8-15),(m8-15,k8-15)
    const uint32_t a_lane_off =
        (uint32_t)(((lane & 7) + ((lane >> 3) & 1) * 8) * HSTR + ((lane >> 4) & 1) * 8);
    // B matrices: (n0-7,k0-7),(n0-7,k8-15),(n8-15,k0-7),(n8-15,k8-15)
    const uint32_t b_lane_off =
        (uint32_t)(((lane & 7) + ((lane >> 4) & 1) * 8) * HSTR + ((lane >> 3) & 1) * 8);

    for (int s = 0; s < nk; s++) {
        asm volatile("cp.async.wait_group 1;\n" ::: "memory");
        __syncthreads();
        if (s + 2 < nk) issue(s + 2);

        const uint32_t aw_base = smem_base + (uint32_t)((s % 3) * STG_B);
        const uint32_t bw_base = aw_base + (uint32_t)(A_H * 2);

        #pragma unroll
        for (int k16 = 0; k16 < 4; k16++) {
            const uint32_t kh = (uint32_t)(k16 * 16);   // halves
            uint32_t a[2][4], b[4][4];
            #pragma unroll
            for (int mt = 0; mt < 2; mt++)
                ldmatrix_x4(a[mt], aw_base +
                    ((uint32_t)((wm * 32 + mt * 16) * HSTR) + kh + a_lane_off) * 2u);
            #pragma unroll
            for (int nb = 0; nb < 4; nb++)
                ldmatrix_x4(b[nb], bw_base +
                    ((uint32_t)((wn * 64 + nb * 16) * HSTR) + kh + b_lane_off) * 2u);
            #pragma unroll
            for (int mt = 0; mt < 2; mt++)
                #pragma unroll
                for (int nb = 0; nb < 4; nb++) {
                    mma_f16(acc[mt][2*nb],     a[mt], b[nb]);
                    mma_f16(acc[mt][2*nb + 1], a[mt], b[nb] + 2);
                }
        }
        __syncthreads();
    }

    if (half_out) {
        __half* C = (__half*)Cv;
        #pragma unroll
        for (int mt = 0; mt < 2; mt++) {
            int r0 = rowBase + wm * 32 + mt * 16 + g4;
            #pragma unroll
            for (int nt = 0; nt < 8; nt++) {
                int c0 = colBase + wn * 64 + nt * 8 + 2 * c4;
                *reinterpret_cast<__half2*>(C + (size_t)r0 * N + c0) =
                    __floats2half2_rn(acc[mt][nt][0], acc[mt][nt][1]);
                *reinterpret_cast<__half2*>(C + (size_t)(r0 + 8) * N + c0) =
                    __floats2half2_rn(acc[mt][nt][2], acc[mt][nt][3]);
            }
        }
    } else {
        float* C = (float*)Cv;
        #pragma unroll
        for (int mt = 0; mt < 2; mt++) {
            int r0 = rowBase + wm * 32 + mt * 16 + g4;
            #pragma unroll
            for (int nt = 0; nt < 8; nt++) {
                int c0 = colBase + wn * 64 + nt * 8 + 2 * c4;
                *reinterpret_cast<float2*>(C + (size_t)r0 * N + c0) =
                    make_float2(acc[mt][nt][0], acc[mt][nt][1]);
                *reinterpret_cast<float2*>(C + (size_t)(r0 + 8) * N + c0) =
                    make_float2(acc[mt][nt][2], acc[mt][nt][3]);
            }
        }
    }
}

// ---------------------------------------------------------------------------
// fp16 flash attention — unchanged R11 (BR=64, 128 threads, 2 CTAs/SM).
// ---------------------------------------------------------------------------
#define FBR 64
#define FSTR 136
#define FWSTR 68
#define KVH (64*FSTR)
#define FLASH_SMEM (4*KVH*2)             // 69632

__global__ void __launch_bounds__(128, 2) flash_h(
    const __half* __restrict__ q, const __half* __restrict__ kv,
    __half* __restrict__ att)
{
    extern __shared__ __half sh[];
    const uint32_t smem_base = (uint32_t)__cvta_generic_to_shared(sh);

    const int tid  = threadIdx.x;
    const int lane = tid & 31;
    const int wid  = tid >> 5;
    const int bx = gridDim.x - 1 - blockIdx.x;
    const int h = blockIdx.y, b = blockIdx.z;
    const int hk = h / REP;
    const int qrow0 = bx * FBR;
    const int c4 = lane & 3;
    const int g4 = lane >> 2;

    {
        const __half* qg = q + ((size_t)(b * TT + qrow0) * HH + h) * HDD;
        #pragma unroll
        for (int i = 0; i < 8; i++) {
            int idx = tid + i * 128;
            int r = idx >> 4, c = idx & 15;
            *reinterpret_cast<uint4*>(sh + r * FSTR + c * 8) =
                *reinterpret_cast<const uint4*>(qg + (size_t)r * HH * HDD + c * 8);
        }
    }
    __syncthreads();

    uint32_t qa[8][4];
    {
        const uint32_t* Qw = reinterpret_cast<const uint32_t*>(sh);
        const int r = wid * 16 + g4;
        #pragma unroll
        for (int ks = 0; ks < 8; ks++) {
            int w = ks * 8 + c4;
            qa[ks][0] = Qw[r * FWSTR + w];
            qa[ks][1] = Qw[(r + 8) * FWSTR + w];
            qa[ks][2] = Qw[r * FWSTR + w + 4];
            qa[ks][3] = Qw[(r + 8) * FWSTR + w + 4];
        }
    }
    __syncthreads();

    auto issue_kv = [&](int kt, int stg) {
        const __half* kg = kv + (size_t)(b * TT + kt * 64) * 1024 + hk * HDD;
        uint32_t ks_u = smem_base + (uint32_t)(stg * 2 * KVH) * 2u;
        uint32_t vs_u = ks_u + (uint32_t)KVH * 2u;
        #pragma unroll
        for (int i = 0; i < 16; i++) {
            int idx = tid + i * 128;
            int r = (idx >> 4) & 63, c = idx & 15;
            if (idx < 1024)
                cp16(ks_u + (uint32_t)(r * FSTR + c * 8) * 2u,
                     kg + (size_t)r * 1024 + c * 8);
            else
                cp16(vs_u + (uint32_t)(r * FSTR + c * 8) * 2u,
                     kg + 512 + (size_t)r * 1024 + c * 8);
        }
        asm volatile("cp.async.commit_group;\n" ::: "memory");
    };

    float o[16][4];
    #pragma unroll
    for (int nt = 0; nt < 16; nt++)
        #pragma unroll
        for (int j = 0; j < 4; j++) o[nt][j] = 0.0f;

    float m0 = -INFINITY, m1 = -INFINITY, l0 = 0.0f, l1 = 0.0f;
    const int r0g = qrow0 + wid * 16 + g4;
    const int r1g = r0g + 8;

    const uint32_t k_lane_off =
        (uint32_t)(((lane & 7) + ((lane >> 4) << 3)) * FSTR + ((lane >> 3) & 1) * 8);

    const int ntile = bx + 1;
    issue_kv(0, 0);

    for (int kt = 0; kt < ntile; kt++) {
        __syncthreads();
        if (kt + 1 < ntile) {
            issue_kv(kt + 1, (kt + 1) & 1);
            asm volatile("cp.async.wait_group 1;\n" ::: "memory");
        } else {
            asm volatile("cp.async.wait_group 0;\n" ::: "memory");
        }
        __syncthreads();

        const uint32_t ks_base = smem_base + (uint32_t)((kt & 1) * 2 * KVH) * 2u;
        const uint32_t vs_base = ks_base + (uint32_t)KVH * 2u;

        float s[8][4];
        #pragma unroll
        for (int nt = 0; nt < 8; nt++)
            #pragma unroll
            for (int j = 0; j < 4; j++) s[nt][j] = 0.0f;

        #pragma unroll
        for (int ks = 0; ks < 8; ks++) {
            #pragma unroll
            for (int np = 0; np < 4; np++) {
                uint32_t bb[4];
                ldmatrix_x4(bb, ks_base +
                    (uint32_t)(np * 16 * FSTR + ks * 16 + k_lane_off) * 2u);
                mma_f16(s[2*np],     qa[ks], bb);
                mma_f16(s[2*np + 1], qa[ks], bb + 2);
            }
        }

        if (kt >= bx) {
            #pragma unroll
            for (int nt = 0; nt < 8; nt++) {
                int c0 = kt * 64 + nt * 8 + 2 * c4;
                if (c0     > r0g) s[nt][0] = -INFINITY;
                if (c0 + 1 > r0g) s[nt][1] = -INFINITY;
                if (c0     > r1g) s[nt][2] = -INFINITY;
                if (c0 + 1 > r1g) s[nt][3] = -INFINITY;
            }
        }

        float mx0 = -INFINITY, mx1 = -INFINITY;
        #pragma unroll
        for (int nt = 0; nt < 8; nt++) {
            mx0 = fmaxf(mx0, fmaxf(s[nt][0], s[nt][1]));
            mx1 = fmaxf(mx1, fmaxf(s[nt][2], s[nt][3]));
        }
        mx0 = fmaxf(mx0, __shfl_xor_sync(0xffffffffu, mx0, 1));
        mx0 = fmaxf(mx0, __shfl_xor_sync(0xffffffffu, mx0, 2));
        mx1 = fmaxf(mx1, __shfl_xor_sync(0xffffffffu, mx1, 1));
        mx1 = fmaxf(mx1, __shfl_xor_sync(0xffffffffu, mx1, 2));

        float nm0 = fmaxf(m0, mx0), nm1 = fmaxf(m1, mx1);
        float al0 = __expf(m0 - nm0), al1 = __expf(m1 - nm1);
        m0 = nm0; m1 = nm1;

        uint32_t ph0[8], ph1[8];
        float ps0 = 0.0f, ps1 = 0.0f;
        #pragma unroll
        for (int nt = 0; nt < 8; nt++) {
            ph0[nt] = packh2(__expf(s[nt][0] - nm0), __expf(s[nt][1] - nm0));
            ph1[nt] = packh2(__expf(s[nt][2] - nm1), __expf(s[nt][3] - nm1));
            float2 f0 = __half22float2(*reinterpret_cast<__half2*>(&ph0[nt]));
            float2 f1 = __half22float2(*reinterpret_cast<__half2*>(&ph1[nt]));
            ps0 += f0.x + f0.y;
            ps1 += f1.x + f1.y;
        }
        ps0 += __shfl_xor_sync(0xffffffffu, ps0, 1);
        ps0 += __shfl_xor_sync(0xffffffffu, ps0, 2);
        ps1 += __shfl_xor_sync(0xffffffffu, ps1, 1);
        ps1 += __shfl_xor_sync(0xffffffffu, ps1, 2);
        l0 = l0 * al0 + ps0;
        l1 = l1 * al1 + ps1;

        #pragma unroll
        for (int nt = 0; nt < 16; nt++) {
            o[nt][0] *= al0; o[nt][1] *= al0;
            o[nt][2] *= al1; o[nt][3] *= al1;
        }

        const int lm = lane >> 3;
        const int lr = lane & 7;
        #pragma unroll
        for (int ks2 = 0; ks2 < 4; ks2++) {
            uint32_t pa[4] = { ph0[2*ks2], ph1[2*ks2], ph0[2*ks2+1], ph1[2*ks2+1] };
            #pragma unroll
            for (int nb = 0; nb < 8; nb++) {
                uint32_t vb[4];
                int srow = ks2 * 16 + (lm & 1) * 8 + lr;
                int dcol = nb * 16 + (lm >> 1) * 8;
                ldmatrix_x4_trans(vb, vs_base + (uint32_t)(srow * FSTR + dcol) * 2u);
                mma_f16(o[2*nb],     pa, vb);
                mma_f16(o[2*nb + 1], pa, vb + 2);
            }
        }
    }

    const float inv0 = 1.0f / l0, inv1 = 1.0f / l1;
    #pragma unroll
    for (int nt2 = 0; nt2 < 16; nt2++) {
        int c = h * HDD + nt2 * 8 + 2 * c4;
        size_t base0 = (size_t)(b * TT + r0g) * (HH * HDD) + c;
        size_t base1 = (size_t)(b * TT + r1g) * (HH * HDD) + c;
        *reinterpret_cast<__half2*>(att + base0) =
            __floats2half2_rn(o[nt2][0] * inv0, o[nt2][1] * inv0);
        *reinterpret_cast<__half2*>(att + base1) =
            __floats2half2_rn(o[nt2][2] * inv1, o[nt2][3] * inv1);
    }
}

// ---------------------------------------------------------------------------
extern "C" void kernel_launch(void* const* d_in, const int* in_sizes, int n_in,
                              void* d_out, int out_size)
{
    const float* x  = (const float*)d_in[0];
    const float* fc = (const float*)d_in[1];
    const float* fs = (const float*)d_in[2];
    // d_in[3] = mask — enforced analytically
    const float* wq = (const float*)d_in[4];
    const float* wk = (const float*)d_in[5];
    const float* wv = (const float*)d_in[6];
    const float* wo = (const float*)d_in[7];
    float* out = (float*)d_out;

    __half *xh, *qh, *kvh, *atth, *wqT, *wkvT, *woT;
    cudaGetSymbolAddress((void**)&xh,   g_xh);
    cudaGetSymbolAddress((void**)&qh,   g_qh);
    cudaGetSymbolAddress((void**)&kvh,  g_kvh);
    cudaGetSymbolAddress((void**)&atth, g_atth);
    cudaGetSymbolAddress((void**)&wqT,  g_wqT);
    cudaGetSymbolAddress((void**)&wkvT, g_wkvT);
    cudaGetSymbolAddress((void**)&woT,  g_woT);

    cudaFuncSetAttribute(gemm_h,  cudaFuncAttributeMaxDynamicSharedMemorySize, GEMM_SMEM);
    cudaFuncSetAttribute(flash_h, cudaFuncAttributeMaxDynamicSharedMemorySize, (int)FLASH_SMEM);

    const int totq = ROWS * HH  * (HDD / 2);
    const int totk = ROWS * HKK * (HDD / 2);

    // 1) all prepasses in ONE launch
    prepass_all<<<dim3(64, 64, 6), dim3(32, 8)>>>(x, xh, wq, wk, wv, wo, wqT, wkvT, woT);

    if (g_fork.ok) {
        cudaEventRecord(g_fork.e_fork, 0);
        cudaStreamWaitEvent(g_fork.s1, g_fork.e_fork, 0);

        gemm_h<<<dim3(DD/GBN, ROWS/GBM), 512, GEMM_SMEM>>>(
            ROWS, DD, DD, xh, wqT, qh, 1);
        rope_h<<<(totq + 255)/256, 256>>>(qh, fc, fs, HH, HH*HDD, totq,
                                          0.08838834764831845f);

        gemm_h<<<dim3(1024/GBN, ROWS/GBM), 512, GEMM_SMEM, g_fork.s1>>>(
            ROWS, 1024, DD, xh, wkvT, kvh, 1);
        rope_h<<<(totk + 255)/256, 256, 0, g_fork.s1>>>(kvh, fc, fs, HKK, 1024, totk, 1.0f);

        cudaEventRecord(g_fork.e_join, g_fork.s1);
        cudaStreamWaitEvent(0, g_fork.e_join, 0);
    } else {
        gemm_h<<<dim3(DD/GBN, ROWS/GBM), 512, GEMM_SMEM>>>(ROWS, DD,   DD, xh, wqT,  qh,  1);
        gemm_h<<<dim3(1024/GBN, ROWS/GBM), 512, GEMM_SMEM>>>(ROWS, 1024, DD, xh, wkvT, kvh, 1);
        rope_h<<<(totq + 255)/256, 256>>>(qh,  fc, fs, HH,  HH*HDD, totq, 0.08838834764831845f);
        rope_h<<<(totk + 255)/256, 256>>>(kvh, fc, fs, HKK, 1024,   totk, 1.0f);
    }

    // flash attention (unchanged R11)
    flash_h<<<dim3(TT/FBR, HH, BB), 128, FLASH_SMEM>>>(qh, kvh, atth);

    // output projection (fp32 out)
    gemm_h<<<dim3(DD/GBN, ROWS/GBM), 512, GEMM_SMEM>>>(ROWS, DD, HH*HDD, atth, woT, out, 0);
}